// round 2
// baseline (speedup 1.0000x reference)
#include <cuda_runtime.h>
#include <math.h>

#define NB 4
#define NL 4096
#define ND 256
#define BLROWS (NB*NL)            // 16384
#define BLD (NB*NL*ND)            // 4194304
#define SCALE 0.0625f             // 256^-0.5

// ---- scratch (static device globals; allocation is forbidden) ----
__device__ float g_qr[BLD], g_qi[BLD], g_kr[BLD], g_ki[BLD], g_vr[BLD], g_vi[BLD];
__device__ float g_s[(size_t)NB*NL*NL];   // 268 MB scores/probs
__device__ float g_or[BLD], g_oi[BLD];

// ============================================================
// Kernel 1: projections  Y = X @ W^T + b   (M=16384, N=K=256)
// blockIdx.z selects which of the 6 projections.
// ============================================================
__global__ __launch_bounds__(256) void proj_kernel(
    const float* __restrict__ q_real, const float* __restrict__ q_imag,
    const float* __restrict__ k_real, const float* __restrict__ k_imag,
    const float* __restrict__ v_real, const float* __restrict__ v_imag,
    const float* __restrict__ Wq, const float* __restrict__ bq,
    const float* __restrict__ Wk, const float* __restrict__ bk,
    const float* __restrict__ Wv, const float* __restrict__ bv)
{
    const float *X, *W, *bias; float* Y;
    switch (blockIdx.z) {
      case 0: X=q_real; W=Wq; bias=bq; Y=g_qr; break;
      case 1: X=q_imag; W=Wq; bias=bq; Y=g_qi; break;
      case 2: X=k_real; W=Wk; bias=bk; Y=g_kr; break;
      case 3: X=k_imag; W=Wk; bias=bk; Y=g_ki; break;
      case 4: X=v_real; W=Wv; bias=bv; Y=g_vr; break;
      default: X=v_imag; W=Wv; bias=bv; Y=g_vi; break;
    }
    __shared__ float As[16][128];
    __shared__ float Bs[16][64];
    const int tid = threadIdx.x;
    const int tx = tid & 15, ty = tid >> 4;
    const int m0 = blockIdx.y * 128, n0 = blockIdx.x * 64;
    const int aRow = tid >> 2, aK = (tid & 3) << 2;
    float c[8][4] = {};
    for (int k0 = 0; k0 < ND; k0 += 16) {
        float4 a0 = *(const float4*)&X[(size_t)(m0+aRow   )*ND + k0 + aK];
        float4 a1 = *(const float4*)&X[(size_t)(m0+aRow+64)*ND + k0 + aK];
        float4 b0 = *(const float4*)&W[(size_t)(n0+aRow   )*ND + k0 + aK];
        __syncthreads();
        As[aK+0][aRow]=a0.x; As[aK+1][aRow]=a0.y; As[aK+2][aRow]=a0.z; As[aK+3][aRow]=a0.w;
        As[aK+0][aRow+64]=a1.x; As[aK+1][aRow+64]=a1.y; As[aK+2][aRow+64]=a1.z; As[aK+3][aRow+64]=a1.w;
        Bs[aK+0][aRow]=b0.x; Bs[aK+1][aRow]=b0.y; Bs[aK+2][aRow]=b0.z; Bs[aK+3][aRow]=b0.w;
        __syncthreads();
        #pragma unroll
        for (int k = 0; k < 16; k++) {
            float4 aA = *(const float4*)&As[k][ty*8];
            float4 aB = *(const float4*)&As[k][ty*8+4];
            float4 bb = *(const float4*)&Bs[k][tx*4];
            float av[8] = {aA.x,aA.y,aA.z,aA.w,aB.x,aB.y,aB.z,aB.w};
            float bv2[4] = {bb.x,bb.y,bb.z,bb.w};
            #pragma unroll
            for (int i = 0; i < 8; i++)
                #pragma unroll
                for (int j = 0; j < 4; j++)
                    c[i][j] = fmaf(av[i], bv2[j], c[i][j]);
        }
    }
    float4 b4 = *(const float4*)&bias[n0 + tx*4];
    #pragma unroll
    for (int i = 0; i < 8; i++) {
        float4 o;
        o.x = c[i][0]+b4.x; o.y = c[i][1]+b4.y; o.z = c[i][2]+b4.z; o.w = c[i][3]+b4.w;
        *(float4*)&Y[(size_t)(m0+ty*8+i)*ND + n0 + tx*4] = o;
    }
}

// ============================================================
// Kernel 2: scores  S = scale*(Qr Kr^T + Qi Ki^T)   per batch
// M=N=4096, K=256 per stream (two sequential phases)
// ============================================================
__global__ __launch_bounds__(256) void scores_kernel()
{
    const int b = blockIdx.z;
    const float* qrp = g_qr + (size_t)b*NL*ND;
    const float* qip = g_qi + (size_t)b*NL*ND;
    const float* krp = g_kr + (size_t)b*NL*ND;
    const float* kip = g_ki + (size_t)b*NL*ND;
    float* S = g_s + (size_t)b*NL*NL;

    __shared__ float As[16][128];
    __shared__ float Bs[16][64];
    const int tid = threadIdx.x;
    const int tx = tid & 15, ty = tid >> 4;
    const int m0 = blockIdx.y * 128, n0 = blockIdx.x * 64;
    const int aRow = tid >> 2, aK = (tid & 3) << 2;
    float c[8][4] = {};
    #pragma unroll
    for (int phase = 0; phase < 2; phase++) {
        const float* A  = phase ? qip : qrp;
        const float* Bm = phase ? kip : krp;
        for (int k0 = 0; k0 < ND; k0 += 16) {
            float4 a0 = *(const float4*)&A [(size_t)(m0+aRow   )*ND + k0 + aK];
            float4 a1 = *(const float4*)&A [(size_t)(m0+aRow+64)*ND + k0 + aK];
            float4 b0 = *(const float4*)&Bm[(size_t)(n0+aRow   )*ND + k0 + aK];
            __syncthreads();
            As[aK+0][aRow]=a0.x; As[aK+1][aRow]=a0.y; As[aK+2][aRow]=a0.z; As[aK+3][aRow]=a0.w;
            As[aK+0][aRow+64]=a1.x; As[aK+1][aRow+64]=a1.y; As[aK+2][aRow+64]=a1.z; As[aK+3][aRow+64]=a1.w;
            Bs[aK+0][aRow]=b0.x; Bs[aK+1][aRow]=b0.y; Bs[aK+2][aRow]=b0.z; Bs[aK+3][aRow]=b0.w;
            __syncthreads();
            #pragma unroll
            for (int k = 0; k < 16; k++) {
                float4 aA = *(const float4*)&As[k][ty*8];
                float4 aB = *(const float4*)&As[k][ty*8+4];
                float4 bb = *(const float4*)&Bs[k][tx*4];
                float av[8] = {aA.x,aA.y,aA.z,aA.w,aB.x,aB.y,aB.z,aB.w};
                float bv2[4] = {bb.x,bb.y,bb.z,bb.w};
                #pragma unroll
                for (int i = 0; i < 8; i++)
                    #pragma unroll
                    for (int j = 0; j < 4; j++)
                        c[i][j] = fmaf(av[i], bv2[j], c[i][j]);
            }
        }
    }
    #pragma unroll
    for (int i = 0; i < 8; i++) {
        float4 o;
        o.x = c[i][0]*SCALE; o.y = c[i][1]*SCALE; o.z = c[i][2]*SCALE; o.w = c[i][3]*SCALE;
        *(float4*)&S[(size_t)(m0+ty*8+i)*NL + n0 + tx*4] = o;
    }
}

// ============================================================
// Kernel 3: row softmax with pad mask (in place on g_s)
// one block = one row of 4096; 256 threads x 16 elems (reg-resident)
// ============================================================
__global__ __launch_bounds__(256) void softmax_kernel(const unsigned char* __restrict__ mask)
{
    __shared__ float sh[8];
    const int row = blockIdx.x;           // 0..16383
    const int b = row >> 12;
    float* S = g_s + (size_t)row * NL;
    const unsigned char* m = mask + (size_t)b * NL;
    const int t = threadIdx.x;

    float v[16];
    #pragma unroll
    for (int j = 0; j < 4; j++) {
        int f4 = t + j*256;               // float4 index
        float4 x = *(const float4*)&S[f4*4];
        uchar4 mk = *(const uchar4*)&m[f4*4];
        v[j*4+0] = mk.x ? -INFINITY : x.x;
        v[j*4+1] = mk.y ? -INFINITY : x.y;
        v[j*4+2] = mk.z ? -INFINITY : x.z;
        v[j*4+3] = mk.w ? -INFINITY : x.w;
    }
    float mx = -INFINITY;
    #pragma unroll
    for (int i = 0; i < 16; i++) mx = fmaxf(mx, v[i]);
    #pragma unroll
    for (int o = 16; o > 0; o >>= 1) mx = fmaxf(mx, __shfl_xor_sync(0xffffffffu, mx, o));
    if ((t & 31) == 0) sh[t >> 5] = mx;
    __syncthreads();
    mx = sh[0];
    #pragma unroll
    for (int i = 1; i < 8; i++) mx = fmaxf(mx, sh[i]);
    __syncthreads();

    float sum = 0.f;
    #pragma unroll
    for (int i = 0; i < 16; i++) { v[i] = __expf(v[i] - mx); sum += v[i]; }
    #pragma unroll
    for (int o = 16; o > 0; o >>= 1) sum += __shfl_xor_sync(0xffffffffu, sum, o);
    if ((t & 31) == 0) sh[t >> 5] = sum;
    __syncthreads();
    sum = 0.f;
    #pragma unroll
    for (int i = 0; i < 8; i++) sum += sh[i];
    const float inv = 1.f / sum;

    #pragma unroll
    for (int j = 0; j < 4; j++) {
        int f4 = t + j*256;
        float4 o;
        o.x = v[j*4+0]*inv; o.y = v[j*4+1]*inv; o.z = v[j*4+2]*inv; o.w = v[j*4+3]*inv;
        *(float4*)&S[f4*4] = o;
    }
}

// ============================================================
// Kernel 4: O = P @ V  (dual streams vr/vi share the P tile)
// per batch: M=4096, N=256, K=4096
// ============================================================
__global__ __launch_bounds__(256) void pv_kernel()
{
    const int b = blockIdx.z;
    const float* P  = g_s  + (size_t)b*NL*NL;
    const float* Vr = g_vr + (size_t)b*NL*ND;
    const float* Vi = g_vi + (size_t)b*NL*ND;
    float* Or = g_or + (size_t)b*NL*ND;
    float* Oi = g_oi + (size_t)b*NL*ND;

    __shared__ float As[16][128];
    __shared__ float Br[16][64];
    __shared__ float Bi[16][64];
    const int tid = threadIdx.x;
    const int tx = tid & 15, ty = tid >> 4;
    const int m0 = blockIdx.y * 128, n0 = blockIdx.x * 64;
    const int aRow = tid >> 2, aK = (tid & 3) << 2;
    const int bK = tid >> 4, bN = (tid & 15) << 2;
    float cr[8][4] = {}, ci[8][4] = {};

    for (int k0 = 0; k0 < NL; k0 += 16) {
        float4 a0 = *(const float4*)&P [(size_t)(m0+aRow   )*NL + k0 + aK];
        float4 a1 = *(const float4*)&P [(size_t)(m0+aRow+64)*NL + k0 + aK];
        float4 r0 = *(const float4*)&Vr[(size_t)(k0+bK)*ND + n0 + bN];
        float4 i0 = *(const float4*)&Vi[(size_t)(k0+bK)*ND + n0 + bN];
        __syncthreads();
        As[aK+0][aRow]=a0.x; As[aK+1][aRow]=a0.y; As[aK+2][aRow]=a0.z; As[aK+3][aRow]=a0.w;
        As[aK+0][aRow+64]=a1.x; As[aK+1][aRow+64]=a1.y; As[aK+2][aRow+64]=a1.z; As[aK+3][aRow+64]=a1.w;
        *(float4*)&Br[bK][bN] = r0;
        *(float4*)&Bi[bK][bN] = i0;
        __syncthreads();
        #pragma unroll
        for (int k = 0; k < 16; k++) {
            float4 aA = *(const float4*)&As[k][ty*8];
            float4 aB = *(const float4*)&As[k][ty*8+4];
            float4 br = *(const float4*)&Br[k][tx*4];
            float4 bi = *(const float4*)&Bi[k][tx*4];
            float av[8]  = {aA.x,aA.y,aA.z,aA.w,aB.x,aB.y,aB.z,aB.w};
            float brv[4] = {br.x,br.y,br.z,br.w};
            float biv[4] = {bi.x,bi.y,bi.z,bi.w};
            #pragma unroll
            for (int i = 0; i < 8; i++) {
                #pragma unroll
                for (int j = 0; j < 4; j++) {
                    cr[i][j] = fmaf(av[i], brv[j], cr[i][j]);
                    ci[i][j] = fmaf(av[i], biv[j], ci[i][j]);
                }
            }
        }
    }
    #pragma unroll
    for (int i = 0; i < 8; i++) {
        float4 o;
        o.x=cr[i][0]; o.y=cr[i][1]; o.z=cr[i][2]; o.w=cr[i][3];
        *(float4*)&Or[(size_t)(m0+ty*8+i)*ND + n0 + tx*4] = o;
        o.x=ci[i][0]; o.y=ci[i][1]; o.z=ci[i][2]; o.w=ci[i][3];
        *(float4*)&Oi[(size_t)(m0+ty*8+i)*ND + n0 + tx*4] = o;
    }
}

// ============================================================
// Kernel 5: layernorm over D=256 + final write
// grid.y = 0 -> real half of d_out, 1 -> imag half
// ============================================================
__global__ __launch_bounds__(256) void ln_kernel(
    const float* __restrict__ gamma, const float* __restrict__ beta,
    float* __restrict__ out)
{
    __shared__ float shs[8], shq[8];
    const int row = blockIdx.x;
    const int z = blockIdx.y;
    const float* X = (z ? g_oi : g_or) + (size_t)row * ND;
    const int t = threadIdx.x;
    float v = X[t];
    float s = v, q = v * v;
    #pragma unroll
    for (int o = 16; o > 0; o >>= 1) {
        s += __shfl_xor_sync(0xffffffffu, s, o);
        q += __shfl_xor_sync(0xffffffffu, q, o);
    }
    if ((t & 31) == 0) { shs[t >> 5] = s; shq[t >> 5] = q; }
    __syncthreads();
    s = 0.f; q = 0.f;
    #pragma unroll
    for (int i = 0; i < 8; i++) { s += shs[i]; q += shq[i]; }
    const float mean = s * (1.f/ND);
    const float var  = q * (1.f/ND) - mean * mean;
    const float rstd = rsqrtf(var + 1e-5f);
    out[(size_t)z*BLD + (size_t)row*ND + t] = (v - mean) * rstd * gamma[t] + beta[t];
}

// ============================================================
extern "C" void kernel_launch(void* const* d_in, const int* in_sizes, int n_in,
                              void* d_out, int out_size)
{
    (void)in_sizes; (void)n_in; (void)out_size;
    const float* q_real = (const float*)d_in[0];
    const float* q_imag = (const float*)d_in[1];
    const float* k_real = (const float*)d_in[2];
    const float* k_imag = (const float*)d_in[3];
    const float* v_real = (const float*)d_in[4];
    const float* v_imag = (const float*)d_in[5];
    const unsigned char* pad_mask = (const unsigned char*)d_in[6];
    const float* Wq = (const float*)d_in[7];
    const float* bq = (const float*)d_in[8];
    const float* Wk = (const float*)d_in[9];
    const float* bk = (const float*)d_in[10];
    const float* Wv = (const float*)d_in[11];
    const float* bv = (const float*)d_in[12];
    const float* gamma = (const float*)d_in[13];
    const float* beta  = (const float*)d_in[14];
    float* out = (float*)d_out;

    proj_kernel<<<dim3(ND/64, BLROWS/128, 6), 256>>>(
        q_real, q_imag, k_real, k_imag, v_real, v_imag,
        Wq, bq, Wk, bk, Wv, bv);
    scores_kernel<<<dim3(NL/64, NL/128, NB), 256>>>();
    softmax_kernel<<<dim3(NB*NL), 256>>>(pad_mask);
    pv_kernel<<<dim3(ND/64, NL/128, NB), 256>>>();
    ln_kernel<<<dim3(NB*NL, 2), 256>>>(gamma, beta, out);
}

// round 4
// speedup vs baseline: 2.8887x; 2.8887x over previous
#include <cuda_runtime.h>
#include <math.h>
#include <stdint.h>

#define NB 4
#define NL 4096
#define ND 256
#define BLD (NB*NL*ND)            // 4194304
#define SCALE 0.0625f

// ---- scratch (static device globals; allocation is forbidden) ----
__device__ __align__(128) float g_qr[BLD], g_qi[BLD], g_kr[BLD], g_ki[BLD];
__device__ __align__(128) float g_vr[BLD], g_vi[BLD];
__device__ __align__(128) float g_vrt[BLD], g_vit[BLD];    // V transposed [b][d][tok]
__device__ __align__(128) float g_or[BLD], g_oi[BLD];
__device__ __align__(128) float g_s[(size_t)NB*NL*NL];     // 268MB scores/probs

__device__ __forceinline__ float to_tf32(float x) {
    float y; asm("cvt.rna.tf32.f32 %0, %1;" : "=f"(y) : "f"(x)); return y;
}

// m16n8k8 tf32 HMMA (sm_80+, no arch-suffix gating)
#define MMA_TF32(c, a, b) \
    asm volatile("mma.sync.aligned.m16n8k8.row.col.f32.tf32.tf32.f32 " \
        "{%0,%1,%2,%3}, {%4,%5,%6,%7}, {%8,%9}, {%0,%1,%2,%3};" \
        : "+f"((c)[0]), "+f"((c)[1]), "+f"((c)[2]), "+f"((c)[3]) \
        : "r"((a)[0]), "r"((a)[1]), "r"((a)[2]), "r"((a)[3]), "r"((b)[0]), "r"((b)[1]))

#define LDT 36                       // padded smem row stride (floats)
#define TILE_F (128*LDT)             // 4608 floats per 128x32 tile
#define SMEM_BYTES (2*2*TILE_F*4)    // A+B, double-buffered: 73728 B

// ---- 128x32 tile: global -> regs -> smem (tf32-rounded) ----
__device__ __forceinline__ void ldg_tile(float4 r[4], const float* __restrict__ p,
                                         size_t ld, int tid) {
    #pragma unroll
    for (int i = 0; i < 4; i++) {
        int pos = tid + i*256, row = pos >> 3, c4 = pos & 7;
        r[i] = *(const float4*)&p[(size_t)row*ld + c4*4];
    }
}
__device__ __forceinline__ void sts_tile(float* s, const float4 r[4], int tid) {
    #pragma unroll
    for (int i = 0; i < 4; i++) {
        int pos = tid + i*256, row = pos >> 3, c4 = pos & 7;
        float4 v = r[i];
        v.x = to_tf32(v.x); v.y = to_tf32(v.y); v.z = to_tf32(v.z); v.w = to_tf32(v.w);
        *(float4*)&s[row*LDT + c4*4] = v;
    }
}

// ---- one 128x128x32 block-tile step; warp tile 32x64 ----
__device__ __forceinline__ void mma_tile(const float* As, const float* Bs,
                                         float c[2][8][4], int wm, int wn, int lane)
{
    const int g = lane >> 2, tg = lane & 3;
    #pragma unroll
    for (int k8 = 0; k8 < 4; k8++) {
        const int k0 = k8*8;
        uint32_t a[2][4];
        #pragma unroll
        for (int i = 0; i < 2; i++) {
            const float* ap = As + (wm + i*16 + g)*LDT + k0 + tg;
            a[i][0] = __float_as_uint(ap[0]);
            a[i][1] = __float_as_uint(ap[8*LDT]);
            a[i][2] = __float_as_uint(ap[4]);
            a[i][3] = __float_as_uint(ap[8*LDT + 4]);
        }
        #pragma unroll
        for (int j = 0; j < 8; j++) {
            const float* bp = Bs + (wn + j*8 + g)*LDT + k0 + tg;
            uint32_t b[2];
            b[0] = __float_as_uint(bp[0]);
            b[1] = __float_as_uint(bp[4]);
            MMA_TF32(c[0][j], a[0], b);
            MMA_TF32(c[1][j], a[1], b);
        }
    }
}

__device__ __forceinline__ void epilogue(float c[2][8][4], float* __restrict__ out,
                                         size_t ldm, int m0, int n0, int wm, int wn,
                                         int lane, float scale, const float* __restrict__ bias)
{
    const int g = lane >> 2, tg = lane & 3;
    #pragma unroll
    for (int i = 0; i < 2; i++) {
        const int r0 = m0 + wm + i*16 + g;
        #pragma unroll
        for (int j = 0; j < 8; j++) {
            const int col = n0 + wn + j*8 + tg*2;
            float b0 = 0.f, b1 = 0.f;
            if (bias) { b0 = bias[col]; b1 = bias[col+1]; }
            float2 v0 = make_float2(c[i][j][0]*scale + b0, c[i][j][1]*scale + b1);
            float2 v1 = make_float2(c[i][j][2]*scale + b0, c[i][j][3]*scale + b1);
            *(float2*)&out[(size_t)r0*ldm + col]     = v0;
            *(float2*)&out[(size_t)(r0+8)*ldm + col] = v1;
        }
    }
}

// ============================================================
// Kernel 1: projections.  grid=(2, 128, 6).  Y = X@W^T + b
// ============================================================
__global__ __launch_bounds__(256) void proj_mma(
    const float* __restrict__ q_real, const float* __restrict__ q_imag,
    const float* __restrict__ k_real, const float* __restrict__ k_imag,
    const float* __restrict__ v_real, const float* __restrict__ v_imag,
    const float* __restrict__ Wq, const float* __restrict__ bq,
    const float* __restrict__ Wk, const float* __restrict__ bk,
    const float* __restrict__ Wv, const float* __restrict__ bv)
{
    extern __shared__ float smf[];
    const int tid = threadIdx.x, lane = tid & 31, wid = tid >> 5;
    const int wm = (wid & 3)*32, wn = (wid >> 2)*64;
    const int n0 = blockIdx.x*128, m0 = blockIdx.y*128, z = blockIdx.z;
    const float *X, *W, *bias; float* Y;
    switch (z) {
      case 0: X=q_real; W=Wq; bias=bq; Y=g_qr; break;
      case 1: X=q_imag; W=Wq; bias=bq; Y=g_qi; break;
      case 2: X=k_real; W=Wk; bias=bk; Y=g_kr; break;
      case 3: X=k_imag; W=Wk; bias=bk; Y=g_ki; break;
      case 4: X=v_real; W=Wv; bias=bv; Y=g_vr; break;
      default: X=v_imag; W=Wv; bias=bv; Y=g_vi; break;
    }
    const float* Ab = X + (size_t)m0*ND;
    const float* Bb = W + (size_t)n0*ND;
    const int CH = 8;
    float c[2][8][4] = {};
    float4 ra[4], rb[4];
    ldg_tile(ra, Ab, ND, tid); ldg_tile(rb, Bb, ND, tid);
    sts_tile(smf, ra, tid); sts_tile(smf + TILE_F, rb, tid);
    ldg_tile(ra, Ab + 32, ND, tid); ldg_tile(rb, Bb + 32, ND, tid);
    __syncthreads();
    for (int ch = 0; ch < CH; ch++) {
        float* base = smf + (ch & 1)*2*TILE_F;
        mma_tile(base, base + TILE_F, c, wm, wn, lane);
        if (ch + 1 < CH) {
            float* d = smf + ((ch+1) & 1)*2*TILE_F;
            sts_tile(d, ra, tid); sts_tile(d + TILE_F, rb, tid);
            if (ch + 2 < CH) {
                ldg_tile(ra, Ab + (ch+2)*32, ND, tid);
                ldg_tile(rb, Bb + (ch+2)*32, ND, tid);
            }
            __syncthreads();
        }
    }
    epilogue(c, Y, ND, m0, n0, wm, wn, lane, 1.f, bias);
}

// ============================================================
// Kernel 2: V transpose [b][tok][d] -> [b][d][tok]
// ============================================================
__global__ __launch_bounds__(256) void transpose_v()
{
    __shared__ float t[32][33];
    const int b = blockIdx.z & 3, z = blockIdx.z >> 2;
    const float* in = (z ? g_vi : g_vr) + (size_t)b*NL*ND;
    float* outp     = (z ? g_vit : g_vrt) + (size_t)b*ND*NL;
    const int tok0 = blockIdx.x*32, d0 = blockIdx.y*32;
    for (int j = threadIdx.y; j < 32; j += 8)
        t[j][threadIdx.x] = in[(size_t)(tok0 + j)*ND + d0 + threadIdx.x];
    __syncthreads();
    for (int j = threadIdx.y; j < 32; j += 8)
        outp[(size_t)(d0 + j)*NL + tok0 + threadIdx.x] = t[threadIdx.x][j];
}

// ============================================================
// Kernel 3: scores.  grid=(32, 32, 4).
// S = scale*(Qr Kr^T + Qi Ki^T); K = 512 (16 chunks, phase switch at 8)
// ============================================================
__global__ __launch_bounds__(256) void scores_mma()
{
    extern __shared__ float smf[];
    const int tid = threadIdx.x, lane = tid & 31, wid = tid >> 5;
    const int wm = (wid & 3)*32, wn = (wid >> 2)*64;
    const int n0 = blockIdx.x*128, m0 = blockIdx.y*128, b = blockIdx.z;
    const float* APh[2] = { g_qr + (size_t)(b*NL + m0)*ND, g_qi + (size_t)(b*NL + m0)*ND };
    const float* BPh[2] = { g_kr + (size_t)(b*NL + n0)*ND, g_ki + (size_t)(b*NL + n0)*ND };
    const int CH = 16;
    float c[2][8][4] = {};
    float4 ra[4], rb[4];
    ldg_tile(ra, APh[0], ND, tid); ldg_tile(rb, BPh[0], ND, tid);
    sts_tile(smf, ra, tid); sts_tile(smf + TILE_F, rb, tid);
    ldg_tile(ra, APh[0] + 32, ND, tid); ldg_tile(rb, BPh[0] + 32, ND, tid);
    __syncthreads();
    for (int ch = 0; ch < CH; ch++) {
        float* base = smf + (ch & 1)*2*TILE_F;
        mma_tile(base, base + TILE_F, c, wm, wn, lane);
        if (ch + 1 < CH) {
            float* d = smf + ((ch+1) & 1)*2*TILE_F;
            sts_tile(d, ra, tid); sts_tile(d + TILE_F, rb, tid);
            if (ch + 2 < CH) {
                const int nc = ch + 2;
                ldg_tile(ra, APh[nc >> 3] + (nc & 7)*32, ND, tid);
                ldg_tile(rb, BPh[nc >> 3] + (nc & 7)*32, ND, tid);
            }
            __syncthreads();
        }
    }
    epilogue(c, g_s + (size_t)b*NL*NL, NL, m0, n0, wm, wn, lane, SCALE, nullptr);
}

// ============================================================
// Kernel 4: softmax with pad mask (in place on g_s)
// ============================================================
__global__ __launch_bounds__(256) void softmax_kernel(const unsigned char* __restrict__ mask)
{
    __shared__ float sh[8];
    const int row = blockIdx.x, b = row >> 12, t = threadIdx.x;
    float* S = g_s + (size_t)row * NL;
    const unsigned char* m = mask + (size_t)b * NL;
    float v[16];
    #pragma unroll
    for (int j = 0; j < 4; j++) {
        int f4 = t + j*256;
        float4 x = *(const float4*)&S[f4*4];
        uchar4 mk = *(const uchar4*)&m[f4*4];
        v[j*4+0] = mk.x ? -INFINITY : x.x;
        v[j*4+1] = mk.y ? -INFINITY : x.y;
        v[j*4+2] = mk.z ? -INFINITY : x.z;
        v[j*4+3] = mk.w ? -INFINITY : x.w;
    }
    float mx = -INFINITY;
    #pragma unroll
    for (int i = 0; i < 16; i++) mx = fmaxf(mx, v[i]);
    #pragma unroll
    for (int o = 16; o > 0; o >>= 1) mx = fmaxf(mx, __shfl_xor_sync(0xffffffffu, mx, o));
    if ((t & 31) == 0) sh[t >> 5] = mx;
    __syncthreads();
    mx = sh[0];
    #pragma unroll
    for (int i = 1; i < 8; i++) mx = fmaxf(mx, sh[i]);
    __syncthreads();
    float sum = 0.f;
    #pragma unroll
    for (int i = 0; i < 16; i++) { v[i] = __expf(v[i] - mx); sum += v[i]; }
    #pragma unroll
    for (int o = 16; o > 0; o >>= 1) sum += __shfl_xor_sync(0xffffffffu, sum, o);
    if ((t & 31) == 0) sh[t >> 5] = sum;
    __syncthreads();
    sum = 0.f;
    #pragma unroll
    for (int i = 0; i < 8; i++) sum += sh[i];
    const float inv = 1.f / sum;
    #pragma unroll
    for (int j = 0; j < 4; j++) {
        int f4 = t + j*256;
        float4 o;
        o.x = v[j*4+0]*inv; o.y = v[j*4+1]*inv; o.z = v[j*4+2]*inv; o.w = v[j*4+3]*inv;
        *(float4*)&S[f4*4] = o;
    }
}

// ============================================================
// Kernel 5: PV.  grid=(2, 32, 8): z = b*2 + stream.
// O = P @ V (via Vt, n-major k-contiguous); K = 4096 (128 chunks)
// ============================================================
__global__ __launch_bounds__(256) void pv_mma()
{
    extern __shared__ float smf[];
    const int tid = threadIdx.x, lane = tid & 31, wid = tid >> 5;
    const int wm = (wid & 3)*32, wn = (wid >> 2)*64;
    const int n0 = blockIdx.x*128, m0 = blockIdx.y*128;
    const int b = blockIdx.z >> 1, stream = blockIdx.z & 1;
    const float* Ab = g_s + (size_t)(b*NL + m0)*NL;
    const float* Bb = (stream ? g_vit : g_vrt) + (size_t)b*ND*NL + (size_t)n0*NL;
    float* Y = (stream ? g_oi : g_or) + (size_t)b*NL*ND;
    const int CH = 128;
    float c[2][8][4] = {};
    float4 ra[4], rb[4];
    ldg_tile(ra, Ab, NL, tid); ldg_tile(rb, Bb, NL, tid);
    sts_tile(smf, ra, tid); sts_tile(smf + TILE_F, rb, tid);
    ldg_tile(ra, Ab + 32, NL, tid); ldg_tile(rb, Bb + 32, NL, tid);
    __syncthreads();
    for (int ch = 0; ch < CH; ch++) {
        float* base = smf + (ch & 1)*2*TILE_F;
        mma_tile(base, base + TILE_F, c, wm, wn, lane);
        if (ch + 1 < CH) {
            float* d = smf + ((ch+1) & 1)*2*TILE_F;
            sts_tile(d, ra, tid); sts_tile(d + TILE_F, rb, tid);
            if (ch + 2 < CH) {
                ldg_tile(ra, Ab + (ch+2)*32, NL, tid);
                ldg_tile(rb, Bb + (ch+2)*32, NL, tid);
            }
            __syncthreads();
        }
    }
    epilogue(c, Y, ND, m0, n0, wm, wn, lane, 1.f, nullptr);
}

// ============================================================
// Kernel 6: layernorm over D=256 + final write
// ============================================================
__global__ __launch_bounds__(256) void ln_kernel(
    const float* __restrict__ gamma, const float* __restrict__ beta,
    float* __restrict__ out)
{
    __shared__ float shs[8], shq[8];
    const int row = blockIdx.x, z = blockIdx.y, t = threadIdx.x;
    const float* X = (z ? g_oi : g_or) + (size_t)row * ND;
    float v = X[t];
    float s = v, q = v * v;
    #pragma unroll
    for (int o = 16; o > 0; o >>= 1) {
        s += __shfl_xor_sync(0xffffffffu, s, o);
        q += __shfl_xor_sync(0xffffffffu, q, o);
    }
    if ((t & 31) == 0) { shs[t >> 5] = s; shq[t >> 5] = q; }
    __syncthreads();
    s = 0.f; q = 0.f;
    #pragma unroll
    for (int i = 0; i < 8; i++) { s += shs[i]; q += shq[i]; }
    const float mean = s * (1.f/ND);
    const float var  = q * (1.f/ND) - mean * mean;
    const float rstd = rsqrtf(var + 1e-5f);
    out[(size_t)z*BLD + (size_t)row*ND + t] = (v - mean) * rstd * gamma[t] + beta[t];
}

// ============================================================
extern "C" void kernel_launch(void* const* d_in, const int* in_sizes, int n_in,
                              void* d_out, int out_size)
{
    (void)in_sizes; (void)n_in; (void)out_size;
    const float* q_real = (const float*)d_in[0];
    const float* q_imag = (const float*)d_in[1];
    const float* k_real = (const float*)d_in[2];
    const float* k_imag = (const float*)d_in[3];
    const float* v_real = (const float*)d_in[4];
    const float* v_imag = (const float*)d_in[5];
    const unsigned char* pad_mask = (const unsigned char*)d_in[6];
    const float* Wq = (const float*)d_in[7];
    const float* bq = (const float*)d_in[8];
    const float* Wk = (const float*)d_in[9];
    const float* bk = (const float*)d_in[10];
    const float* Wv = (const float*)d_in[11];
    const float* bv = (const float*)d_in[12];
    const float* gamma = (const float*)d_in[13];
    const float* beta  = (const float*)d_in[14];
    float* out = (float*)d_out;

    cudaFuncSetAttribute(proj_mma,   cudaFuncAttributeMaxDynamicSharedMemorySize, SMEM_BYTES);
    cudaFuncSetAttribute(scores_mma, cudaFuncAttributeMaxDynamicSharedMemorySize, SMEM_BYTES);
    cudaFuncSetAttribute(pv_mma,     cudaFuncAttributeMaxDynamicSharedMemorySize, SMEM_BYTES);

    proj_mma<<<dim3(2, 128, 6), 256, SMEM_BYTES>>>(q_real, q_imag, k_real, k_imag,
                                                   v_real, v_imag, Wq, bq, Wk, bk, Wv, bv);
    transpose_v<<<dim3(NL/32, ND/32, 8), dim3(32, 8)>>>();
    scores_mma<<<dim3(32, 32, NB), 256, SMEM_BYTES>>>();
    softmax_kernel<<<NB*NL, 256>>>(pad_mask);
    pv_mma<<<dim3(2, 32, NB*2), 256, SMEM_BYTES>>>();
    ln_kernel<<<dim3(NB*NL, 2), 256>>>(gamma, beta, out);
}

// round 5
// speedup vs baseline: 3.1544x; 1.0920x over previous
#include <cuda_runtime.h>
#include <math.h>
#include <stdint.h>

#define NB 4
#define NL 4096
#define ND 256
#define BLD (NB*NL*ND)
#define SCALE 0.0625f

// ---- scratch (static device globals; allocation is forbidden) ----
__device__ __align__(128) float g_qr[BLD], g_qi[BLD], g_kr[BLD], g_ki[BLD];
__device__ __align__(128) float g_vr[BLD], g_vi[BLD];
__device__ __align__(128) float g_vrt[BLD], g_vit[BLD];    // V transposed [b][d][tok]
__device__ __align__(128) float g_s[(size_t)NB*NL*NL];     // 268MB scores/probs

__device__ __forceinline__ float to_tf32(float x) {
    float y; asm("cvt.rna.tf32.f32 %0, %1;" : "=f"(y) : "f"(x)); return y;
}
__device__ __forceinline__ uint32_t smem_u32(const void* p) {
    uint32_t a;
    asm("{ .reg .u64 t; cvta.to.shared.u64 t, %1; cvt.u32.u64 %0, t; }" : "=r"(a) : "l"(p));
    return a;
}

#define MMA_TF32(c, a, b) \
    asm volatile("mma.sync.aligned.m16n8k8.row.col.f32.tf32.tf32.f32 " \
        "{%0,%1,%2,%3}, {%4,%5,%6,%7}, {%8,%9}, {%0,%1,%2,%3};" \
        : "+f"((c)[0]), "+f"((c)[1]), "+f"((c)[2]), "+f"((c)[3]) \
        : "r"((a)[0]), "r"((a)[1]), "r"((a)[2]), "r"((a)[3]), "r"((b)[0]), "r"((b)[1]))

#define CP_COMMIT asm volatile("cp.async.commit_group;" ::: "memory")
#define CP_WAIT1  asm volatile("cp.async.wait_group 1;" ::: "memory")
#define CP_WAIT0  asm volatile("cp.async.wait_group 0;" ::: "memory")

#define LDT 36                    // padded smem row stride (floats)
#define ATILE_F (128*LDT)         // 4608
#define BTILE_F (256*LDT)         // 9216
#define BUF_F (ATILE_F + BTILE_F) // 13824 floats / 55296 B per stage
#define SMEM_BYTES (2*BUF_F*4)    // 110592 B

// ---- A tile 128x32: global -> regs -> smem (tf32-rounded) ----
__device__ __forceinline__ void ldgA(float4 r[4], const float* __restrict__ p,
                                     size_t ld, int tid) {
    #pragma unroll
    for (int i = 0; i < 4; i++) {
        int pos = tid + i*256, row = pos >> 3, c4 = pos & 7;
        r[i] = *(const float4*)&p[(size_t)row*ld + c4*4];
    }
}
__device__ __forceinline__ void stsA(float* s, const float4 r[4], int tid) {
    #pragma unroll
    for (int i = 0; i < 4; i++) {
        int pos = tid + i*256, row = pos >> 3, c4 = pos & 7;
        float4 v = r[i];
        v.x = to_tf32(v.x); v.y = to_tf32(v.y); v.z = to_tf32(v.z); v.w = to_tf32(v.w);
        *(float4*)&s[row*LDT + c4*4] = v;
    }
}
// ---- B tile 256x32: cp.async raw fp32 (cvt at fragment load) ----
__device__ __forceinline__ void cpasyncB(uint32_t dstbase, const float* __restrict__ p,
                                         size_t ld, int tid) {
    #pragma unroll
    for (int i = 0; i < 8; i++) {
        int pos = tid + i*256, row = pos >> 3, c4 = pos & 7;
        uint32_t dst = dstbase + (uint32_t)(row*LDT + c4*4)*4u;
        const float* src = p + (size_t)row*ld + c4*4;
        asm volatile("cp.async.cg.shared.global [%0], [%1], 16;" :: "r"(dst), "l"(src));
    }
}

// ---- one 128x256x32 block step; warp tile 64x64 ----
__device__ __forceinline__ void mma_block(const float* As, const float* Bs,
                                          float c[4][8][4], int wm, int wn, int lane)
{
    const int g = lane >> 2, tg = lane & 3;
    #pragma unroll
    for (int k8 = 0; k8 < 4; k8++) {
        const int k0 = k8*8;
        uint32_t a[4][4];
        #pragma unroll
        for (int i = 0; i < 4; i++) {
            const float* ap = As + (wm + i*16 + g)*LDT + k0 + tg;
            a[i][0] = __float_as_uint(ap[0]);
            a[i][1] = __float_as_uint(ap[8*LDT]);
            a[i][2] = __float_as_uint(ap[4]);
            a[i][3] = __float_as_uint(ap[8*LDT + 4]);
        }
        #pragma unroll
        for (int j = 0; j < 8; j++) {
            const float* bp = Bs + (wn + j*8 + g)*LDT + k0 + tg;
            uint32_t b[2];
            b[0] = __float_as_uint(to_tf32(bp[0]));
            b[1] = __float_as_uint(to_tf32(bp[4]));
            #pragma unroll
            for (int i = 0; i < 4; i++) MMA_TF32(c[i][j], a[i], b);
        }
    }
}

// generic epilogue (proj/scores)
__device__ __forceinline__ void epilogue(float c[4][8][4], float* __restrict__ out,
                                         size_t ldm, int m0, int n0, int wm, int wn,
                                         int lane, float scale, const float* __restrict__ bias)
{
    const int g = lane >> 2, tg = lane & 3;
    #pragma unroll
    for (int i = 0; i < 4; i++) {
        const int r0 = m0 + wm + i*16 + g;
        #pragma unroll
        for (int j = 0; j < 8; j++) {
            const int col = n0 + wn + j*8 + tg*2;
            float b0 = 0.f, b1 = 0.f;
            if (bias) { b0 = bias[col]; b1 = bias[col+1]; }
            float2 v0 = make_float2(c[i][j][0]*scale + b0, c[i][j][1]*scale + b1);
            float2 v1 = make_float2(c[i][j][2]*scale + b0, c[i][j][3]*scale + b1);
            *(float2*)&out[(size_t)r0*ldm + col]     = v0;
            *(float2*)&out[(size_t)(r0+8)*ldm + col] = v1;
        }
    }
}

// PV epilogue: cross-warp LayerNorm over the 256 block cols, then store
__device__ __forceinline__ void ln_epilogue(float c[4][8][4], float* red,
                                            const float* __restrict__ gamma,
                                            const float* __restrict__ beta,
                                            float* __restrict__ Y,
                                            int wm, int wn, int lane, int tid, int wid)
{
    const int g = lane >> 2, tg = lane & 3;
    const int wg = wid >> 1;          // n-warp group 0..3
    __syncthreads();                  // main loop done; smem free
    red[1280 + tid] = gamma[tid];     // tid<256 covers all cols
    red[1536 + tid] = beta[tid];
    #pragma unroll
    for (int i = 0; i < 4; i++) {
        const int rl = wm + i*16 + g;
        float s0 = 0.f, q0 = 0.f, s1 = 0.f, q1 = 0.f;
        #pragma unroll
        for (int j = 0; j < 8; j++) {
            s0 += c[i][j][0] + c[i][j][1];
            q0 += c[i][j][0]*c[i][j][0] + c[i][j][1]*c[i][j][1];
            s1 += c[i][j][2] + c[i][j][3];
            q1 += c[i][j][2]*c[i][j][2] + c[i][j][3]*c[i][j][3];
        }
        #pragma unroll
        for (int o = 1; o < 4; o <<= 1) {
            s0 += __shfl_xor_sync(0xffffffffu, s0, o);
            q0 += __shfl_xor_sync(0xffffffffu, q0, o);
            s1 += __shfl_xor_sync(0xffffffffu, s1, o);
            q1 += __shfl_xor_sync(0xffffffffu, q1, o);
        }
        if (tg == 0) {
            red[wg*128 + rl]       = s0; red[512 + wg*128 + rl]     = q0;
            red[wg*128 + rl + 8]   = s1; red[512 + wg*128 + rl + 8] = q1;
        }
    }
    __syncthreads();
    if (tid < 128) {
        float s = red[tid] + red[128+tid] + red[256+tid] + red[384+tid];
        float q = red[512+tid] + red[640+tid] + red[768+tid] + red[896+tid];
        float mean = s * (1.f/256.f);
        red[1024 + tid] = mean;
        red[1152 + tid] = rsqrtf(q * (1.f/256.f) - mean*mean + 1e-5f);
    }
    __syncthreads();
    #pragma unroll
    for (int i = 0; i < 4; i++) {
        const int rl = wm + i*16 + g;
        const float m0v = red[1024 + rl],     rs0 = red[1152 + rl];
        const float m1v = red[1024 + rl + 8], rs1 = red[1152 + rl + 8];
        #pragma unroll
        for (int j = 0; j < 8; j++) {
            const int col = wn + j*8 + tg*2;
            const float ga0 = red[1280 + col], ga1 = red[1281 + col];
            const float be0 = red[1536 + col], be1 = red[1537 + col];
            float2 v0 = make_float2((c[i][j][0]-m0v)*rs0*ga0 + be0,
                                    (c[i][j][1]-m0v)*rs0*ga1 + be1);
            float2 v1 = make_float2((c[i][j][2]-m1v)*rs1*ga0 + be0,
                                    (c[i][j][3]-m1v)*rs1*ga1 + be1);
            *(float2*)&Y[(size_t)rl*ND + col]     = v0;
            *(float2*)&Y[(size_t)(rl+8)*ND + col] = v1;
        }
    }
}

// ============================================================
// Kernel 1: projections.  grid=(128, 6). block tile 128x256
// ============================================================
__global__ __launch_bounds__(256, 1) void proj_mma(
    const float* __restrict__ q_real, const float* __restrict__ q_imag,
    const float* __restrict__ k_real, const float* __restrict__ k_imag,
    const float* __restrict__ v_real, const float* __restrict__ v_imag,
    const float* __restrict__ Wq, const float* __restrict__ bq,
    const float* __restrict__ Wk, const float* __restrict__ bk,
    const float* __restrict__ Wv, const float* __restrict__ bv)
{
    extern __shared__ float smf[];
    const uint32_t sb = smem_u32(smf);
    const int tid = threadIdx.x, lane = tid & 31, wid = tid >> 5;
    const int wm = (wid & 1)*64, wn = (wid >> 1)*64;
    const int m0 = blockIdx.x*128, z = blockIdx.y;
    const float *X, *W, *bias; float* Y;
    switch (z) {
      case 0: X=q_real; W=Wq; bias=bq; Y=g_qr; break;
      case 1: X=q_imag; W=Wq; bias=bq; Y=g_qi; break;
      case 2: X=k_real; W=Wk; bias=bk; Y=g_kr; break;
      case 3: X=k_imag; W=Wk; bias=bk; Y=g_ki; break;
      case 4: X=v_real; W=Wv; bias=bv; Y=g_vr; break;
      default: X=v_imag; W=Wv; bias=bv; Y=g_vi; break;
    }
    const float* Ab = X + (size_t)m0*ND;
    const int CH = 8;
    float c[4][8][4] = {};
    float4 ra[4];
    cpasyncB(sb + ATILE_F*4, W, ND, tid); CP_COMMIT;
    ldgA(ra, Ab, ND, tid);
    stsA(smf, ra, tid);
    cpasyncB(sb + (BUF_F + ATILE_F)*4, W + 32, ND, tid); CP_COMMIT;
    ldgA(ra, Ab + 32, ND, tid);
    CP_WAIT1;
    __syncthreads();
    for (int ch = 0; ch < CH; ch++) {
        float* base = smf + (ch & 1)*BUF_F;
        mma_block(base, base + ATILE_F, c, wm, wn, lane);
        if (ch + 1 < CH) {
            stsA(smf + ((ch+1) & 1)*BUF_F, ra, tid);
            __syncthreads();
            if (ch + 2 < CH) {
                cpasyncB(sb + ((ch&1)*BUF_F + ATILE_F)*4, W + (ch+2)*32, ND, tid); CP_COMMIT;
                ldgA(ra, Ab + (ch+2)*32, ND, tid);
                CP_WAIT1;
            } else CP_WAIT0;
            __syncthreads();
        }
    }
    epilogue(c, Y, ND, m0, 0, wm, wn, lane, 1.f, bias);
}

// ============================================================
// Kernel 2: V transpose [b][tok][d] -> [b][d][tok]
// ============================================================
__global__ __launch_bounds__(256) void transpose_v()
{
    __shared__ float t[32][33];
    const int b = blockIdx.z & 3, z = blockIdx.z >> 2;
    const float* in = (z ? g_vi : g_vr) + (size_t)b*NL*ND;
    float* outp     = (z ? g_vit : g_vrt) + (size_t)b*ND*NL;
    const int tok0 = blockIdx.x*32, d0 = blockIdx.y*32;
    for (int j = threadIdx.y; j < 32; j += 8)
        t[j][threadIdx.x] = in[(size_t)(tok0 + j)*ND + d0 + threadIdx.x];
    __syncthreads();
    for (int j = threadIdx.y; j < 32; j += 8)
        outp[(size_t)(d0 + j)*NL + tok0 + threadIdx.x] = t[threadIdx.x][j];
}

// ============================================================
// Kernel 3: scores.  grid=(16, 32, 4). block 128x256, K=512
// ============================================================
__global__ __launch_bounds__(256, 1) void scores_mma()
{
    extern __shared__ float smf[];
    const uint32_t sb = smem_u32(smf);
    const int tid = threadIdx.x, lane = tid & 31, wid = tid >> 5;
    const int wm = (wid & 1)*64, wn = (wid >> 1)*64;
    const int n0 = blockIdx.x*256, m0 = blockIdx.y*128, b = blockIdx.z;
    const float* APh[2] = { g_qr + (size_t)(b*NL + m0)*ND, g_qi + (size_t)(b*NL + m0)*ND };
    const float* BPh[2] = { g_kr + (size_t)(b*NL + n0)*ND, g_ki + (size_t)(b*NL + n0)*ND };
    const int CH = 16;
    float c[4][8][4] = {};
    float4 ra[4];
    cpasyncB(sb + ATILE_F*4, BPh[0], ND, tid); CP_COMMIT;
    ldgA(ra, APh[0], ND, tid);
    stsA(smf, ra, tid);
    cpasyncB(sb + (BUF_F + ATILE_F)*4, BPh[0] + 32, ND, tid); CP_COMMIT;
    ldgA(ra, APh[0] + 32, ND, tid);
    CP_WAIT1;
    __syncthreads();
    for (int ch = 0; ch < CH; ch++) {
        float* base = smf + (ch & 1)*BUF_F;
        mma_block(base, base + ATILE_F, c, wm, wn, lane);
        if (ch + 1 < CH) {
            stsA(smf + ((ch+1) & 1)*BUF_F, ra, tid);
            __syncthreads();
            if (ch + 2 < CH) {
                const int nc = ch + 2;
                cpasyncB(sb + ((ch&1)*BUF_F + ATILE_F)*4, BPh[nc >> 3] + (nc & 7)*32, ND, tid); CP_COMMIT;
                ldgA(ra, APh[nc >> 3] + (nc & 7)*32, ND, tid);
                CP_WAIT1;
            } else CP_WAIT0;
            __syncthreads();
        }
    }
    epilogue(c, g_s + (size_t)b*NL*NL, NL, m0, n0, wm, wn, lane, SCALE, nullptr);
}

// ============================================================
// Kernel 4: softmax with pad mask (in place on g_s)
// ============================================================
__global__ __launch_bounds__(256) void softmax_kernel(const unsigned char* __restrict__ mask)
{
    __shared__ float sh[8];
    const int row = blockIdx.x, b = row >> 12, t = threadIdx.x;
    float* S = g_s + (size_t)row * NL;
    const unsigned char* m = mask + (size_t)b * NL;
    float v[16];
    #pragma unroll
    for (int j = 0; j < 4; j++) {
        int f4 = t + j*256;
        float4 x = *(const float4*)&S[f4*4];
        uchar4 mk = *(const uchar4*)&m[f4*4];
        v[j*4+0] = mk.x ? -INFINITY : x.x;
        v[j*4+1] = mk.y ? -INFINITY : x.y;
        v[j*4+2] = mk.z ? -INFINITY : x.z;
        v[j*4+3] = mk.w ? -INFINITY : x.w;
    }
    float mx = -INFINITY;
    #pragma unroll
    for (int i = 0; i < 16; i++) mx = fmaxf(mx, v[i]);
    #pragma unroll
    for (int o = 16; o > 0; o >>= 1) mx = fmaxf(mx, __shfl_xor_sync(0xffffffffu, mx, o));
    if ((t & 31) == 0) sh[t >> 5] = mx;
    __syncthreads();
    mx = sh[0];
    #pragma unroll
    for (int i = 1; i < 8; i++) mx = fmaxf(mx, sh[i]);
    __syncthreads();
    float sum = 0.f;
    #pragma unroll
    for (int i = 0; i < 16; i++) { v[i] = __expf(v[i] - mx); sum += v[i]; }
    #pragma unroll
    for (int o = 16; o > 0; o >>= 1) sum += __shfl_xor_sync(0xffffffffu, sum, o);
    if ((t & 31) == 0) sh[t >> 5] = sum;
    __syncthreads();
    sum = 0.f;
    #pragma unroll
    for (int i = 0; i < 8; i++) sum += sh[i];
    const float inv = 1.f / sum;
    #pragma unroll
    for (int j = 0; j < 4; j++) {
        int f4 = t + j*256;
        float4 o;
        o.x = v[j*4+0]*inv; o.y = v[j*4+1]*inv; o.z = v[j*4+2]*inv; o.w = v[j*4+3]*inv;
        *(float4*)&S[f4*4] = o;
    }
}

// ============================================================
// Kernel 5: PV fused (both streams) + LayerNorm.
// grid=(2 streams, 32 mtiles, 4 batch). K=4096 (128 chunks)
// ============================================================
__global__ __launch_bounds__(256, 1) void pv_mma(
    const float* __restrict__ gamma, const float* __restrict__ beta,
    float* __restrict__ out)
{
    extern __shared__ float smf[];
    const uint32_t sb = smem_u32(smf);
    const int tid = threadIdx.x, lane = tid & 31, wid = tid >> 5;
    const int wm = (wid & 1)*64, wn = (wid >> 1)*64;
    const int stream = blockIdx.x, m0 = blockIdx.y*128, b = blockIdx.z;
    const float* Ab = g_s + (size_t)(b*NL + m0)*NL;
    const float* Bb = (stream ? g_vit : g_vrt) + (size_t)b*ND*NL;
    float* Y = out + (size_t)stream*BLD + (size_t)(b*NL + m0)*ND;
    const int CH = 128;
    float c[4][8][4] = {};
    float4 ra[4];
    cpasyncB(sb + ATILE_F*4, Bb, NL, tid); CP_COMMIT;
    ldgA(ra, Ab, NL, tid);
    stsA(smf, ra, tid);
    cpasyncB(sb + (BUF_F + ATILE_F)*4, Bb + 32, NL, tid); CP_COMMIT;
    ldgA(ra, Ab + 32, NL, tid);
    CP_WAIT1;
    __syncthreads();
    for (int ch = 0; ch < CH; ch++) {
        float* base = smf + (ch & 1)*BUF_F;
        mma_block(base, base + ATILE_F, c, wm, wn, lane);
        if (ch + 1 < CH) {
            stsA(smf + ((ch+1) & 1)*BUF_F, ra, tid);
            __syncthreads();
            if (ch + 2 < CH) {
                cpasyncB(sb + ((ch&1)*BUF_F + ATILE_F)*4, Bb + (ch+2)*32, NL, tid); CP_COMMIT;
                ldgA(ra, Ab + (ch+2)*32, NL, tid);
                CP_WAIT1;
            } else CP_WAIT0;
            __syncthreads();
        }
    }
    ln_epilogue(c, smf, gamma, beta, Y, wm, wn, lane, tid, wid);
}

// ============================================================
extern "C" void kernel_launch(void* const* d_in, const int* in_sizes, int n_in,
                              void* d_out, int out_size)
{
    (void)in_sizes; (void)n_in; (void)out_size;
    const float* q_real = (const float*)d_in[0];
    const float* q_imag = (const float*)d_in[1];
    const float* k_real = (const float*)d_in[2];
    const float* k_imag = (const float*)d_in[3];
    const float* v_real = (const float*)d_in[4];
    const float* v_imag = (const float*)d_in[5];
    const unsigned char* pad_mask = (const unsigned char*)d_in[6];
    const float* Wq = (const float*)d_in[7];
    const float* bq = (const float*)d_in[8];
    const float* Wk = (const float*)d_in[9];
    const float* bk = (const float*)d_in[10];
    const float* Wv = (const float*)d_in[11];
    const float* bv = (const float*)d_in[12];
    const float* gamma = (const float*)d_in[13];
    const float* beta  = (const float*)d_in[14];
    float* out = (float*)d_out;

    cudaFuncSetAttribute(proj_mma,   cudaFuncAttributeMaxDynamicSharedMemorySize, SMEM_BYTES);
    cudaFuncSetAttribute(scores_mma, cudaFuncAttributeMaxDynamicSharedMemorySize, SMEM_BYTES);
    cudaFuncSetAttribute(pv_mma,     cudaFuncAttributeMaxDynamicSharedMemorySize, SMEM_BYTES);

    proj_mma<<<dim3(128, 6), 256, SMEM_BYTES>>>(q_real, q_imag, k_real, k_imag,
                                                v_real, v_imag, Wq, bq, Wk, bk, Wv, bv);
    transpose_v<<<dim3(NL/32, ND/32, 8), dim3(32, 8)>>>();
    scores_mma<<<dim3(16, 32, NB), 256, SMEM_BYTES>>>();
    softmax_kernel<<<NB*NL, 256>>>(pad_mask);
    pv_mma<<<dim3(2, 32, NB), 256, SMEM_BYTES>>>(gamma, beta, out);
}

// round 6
// speedup vs baseline: 3.2880x; 1.0423x over previous
#include <cuda_runtime.h>
#include <math.h>
#include <stdint.h>

#define NB 4
#define NL 4096
#define ND 256
#define BLD (NB*NL*ND)
#define SCALE 0.0625f

// ---- scratch (static device globals; allocation is forbidden) ----
__device__ __align__(128) float g_qr[BLD], g_qi[BLD], g_kr[BLD], g_ki[BLD];
__device__ __align__(128) float g_vr[BLD], g_vi[BLD];
__device__ __align__(128) float g_vrt[BLD], g_vit[BLD];    // V transposed [b][d][tok]
__device__ __align__(128) float g_s[(size_t)NB*NL*NL];     // 268MB scores/probs

__device__ __forceinline__ float to_tf32(float x) {
    float y; asm("cvt.rna.tf32.f32 %0, %1;" : "=f"(y) : "f"(x)); return y;
}
__device__ __forceinline__ uint32_t smem_u32(const void* p) {
    uint32_t a;
    asm("{ .reg .u64 t; cvta.to.shared.u64 t, %1; cvt.u32.u64 %0, t; }" : "=r"(a) : "l"(p));
    return a;
}

#define MMA_TF32(c, a, b) \
    asm volatile("mma.sync.aligned.m16n8k8.row.col.f32.tf32.tf32.f32 " \
        "{%0,%1,%2,%3}, {%4,%5,%6,%7}, {%8,%9}, {%0,%1,%2,%3};" \
        : "+f"((c)[0]), "+f"((c)[1]), "+f"((c)[2]), "+f"((c)[3]) \
        : "r"((a)[0]), "r"((a)[1]), "r"((a)[2]), "r"((a)[3]), "r"((b)[0]), "r"((b)[1]))

#define CP_COMMIT asm volatile("cp.async.commit_group;" ::: "memory")
#define CP_WAIT2  asm volatile("cp.async.wait_group 2;" ::: "memory")
#define CP_WAIT1  asm volatile("cp.async.wait_group 1;" ::: "memory")
#define CP_WAIT0  asm volatile("cp.async.wait_group 0;" ::: "memory")

#define LDT 36                    // padded smem row stride (floats)
#define ATILE_F (128*LDT)         // 4608
#define BTILE_F (256*LDT)         // 9216
#define BUF_F (ATILE_F + BTILE_F) // 13824 floats per stage
#define NSTAGE 3
#define SMEM_BYTES (NSTAGE*BUF_F*4)   // 165888 B

// ---- cp.async tile loaders (raw fp32; operands are pre-rounded to tf32) ----
__device__ __forceinline__ void cpasyncA(uint32_t dstbase, const float* __restrict__ p,
                                         size_t ld, int tid) {
    #pragma unroll
    for (int i = 0; i < 4; i++) {
        int pos = tid + i*256, row = pos >> 3, c4 = pos & 7;
        uint32_t dst = dstbase + (uint32_t)(row*LDT + c4*4)*4u;
        asm volatile("cp.async.cg.shared.global [%0], [%1], 16;"
                     :: "r"(dst), "l"(p + (size_t)row*ld + c4*4));
    }
}
__device__ __forceinline__ void cpasyncB(uint32_t dstbase, const float* __restrict__ p,
                                         size_t ld, int tid) {
    #pragma unroll
    for (int i = 0; i < 8; i++) {
        int pos = tid + i*256, row = pos >> 3, c4 = pos & 7;
        uint32_t dst = dstbase + (uint32_t)(row*LDT + c4*4)*4u;
        asm volatile("cp.async.cg.shared.global [%0], [%1], 16;"
                     :: "r"(dst), "l"(p + (size_t)row*ld + c4*4));
    }
}

// ---- one 128x256x32 block step; warp tile 64x64 ----
template<bool CVT>
__device__ __forceinline__ void mma_block(const float* As, const float* Bs,
                                          float c[4][8][4], int wm, int wn, int lane)
{
    const int g = lane >> 2, tg = lane & 3;
    #pragma unroll
    for (int k8 = 0; k8 < 4; k8++) {
        const int k0 = k8*8;
        uint32_t a[4][4];
        #pragma unroll
        for (int i = 0; i < 4; i++) {
            const float* ap = As + (wm + i*16 + g)*LDT + k0 + tg;
            float f0 = ap[0], f1 = ap[8*LDT], f2 = ap[4], f3 = ap[8*LDT + 4];
            if (CVT) { f0 = to_tf32(f0); f1 = to_tf32(f1); f2 = to_tf32(f2); f3 = to_tf32(f3); }
            a[i][0] = __float_as_uint(f0);
            a[i][1] = __float_as_uint(f1);
            a[i][2] = __float_as_uint(f2);
            a[i][3] = __float_as_uint(f3);
        }
        #pragma unroll
        for (int j = 0; j < 8; j++) {
            const float* bp = Bs + (wn + j*8 + g)*LDT + k0 + tg;
            float f0 = bp[0], f1 = bp[4];
            if (CVT) { f0 = to_tf32(f0); f1 = to_tf32(f1); }
            uint32_t b[2] = { __float_as_uint(f0), __float_as_uint(f1) };
            #pragma unroll
            for (int i = 0; i < 4; i++) MMA_TF32(c[i][j], a[i], b);
        }
    }
}

// pipeline wait: chunk ch ready (3-stage, in-order group completion)
__device__ __forceinline__ void pipe_wait(int ch, int CH) {
    if (ch + NSTAGE <= CH) CP_WAIT2;
    else if (ch + 2 == CH) CP_WAIT1;
    else CP_WAIT0;
}

// generic epilogue (proj/scores).  ROUND: store tf32-rounded values.
template<bool ROUND>
__device__ __forceinline__ void epilogue(float c[4][8][4], float* __restrict__ out,
                                         size_t ldm, int m0, int n0, int wm, int wn,
                                         int lane, float scale, const float* __restrict__ bias)
{
    const int g = lane >> 2, tg = lane & 3;
    #pragma unroll
    for (int i = 0; i < 4; i++) {
        const int r0 = m0 + wm + i*16 + g;
        #pragma unroll
        for (int j = 0; j < 8; j++) {
            const int col = n0 + wn + j*8 + tg*2;
            float b0 = 0.f, b1 = 0.f;
            if (bias) { b0 = bias[col]; b1 = bias[col+1]; }
            float v00 = c[i][j][0]*scale + b0, v01 = c[i][j][1]*scale + b1;
            float v10 = c[i][j][2]*scale + b0, v11 = c[i][j][3]*scale + b1;
            if (ROUND) { v00 = to_tf32(v00); v01 = to_tf32(v01);
                         v10 = to_tf32(v10); v11 = to_tf32(v11); }
            *(float2*)&out[(size_t)r0*ldm + col]     = make_float2(v00, v01);
            *(float2*)&out[(size_t)(r0+8)*ldm + col] = make_float2(v10, v11);
        }
    }
}

// PV epilogue: cross-warp LayerNorm over the 256 block cols, then store
__device__ __forceinline__ void ln_epilogue(float c[4][8][4], float* red,
                                            const float* __restrict__ gamma,
                                            const float* __restrict__ beta,
                                            float* __restrict__ Y,
                                            int wm, int wn, int lane, int tid, int wid)
{
    const int g = lane >> 2, tg = lane & 3;
    const int wg = wid >> 1;          // n-warp group 0..3
    __syncthreads();                  // main loop done; smem free
    red[1280 + tid] = gamma[tid];
    red[1536 + tid] = beta[tid];
    #pragma unroll
    for (int i = 0; i < 4; i++) {
        const int rl = wm + i*16 + g;
        float s0 = 0.f, q0 = 0.f, s1 = 0.f, q1 = 0.f;
        #pragma unroll
        for (int j = 0; j < 8; j++) {
            s0 += c[i][j][0] + c[i][j][1];
            q0 += c[i][j][0]*c[i][j][0] + c[i][j][1]*c[i][j][1];
            s1 += c[i][j][2] + c[i][j][3];
            q1 += c[i][j][2]*c[i][j][2] + c[i][j][3]*c[i][j][3];
        }
        #pragma unroll
        for (int o = 1; o < 4; o <<= 1) {
            s0 += __shfl_xor_sync(0xffffffffu, s0, o);
            q0 += __shfl_xor_sync(0xffffffffu, q0, o);
            s1 += __shfl_xor_sync(0xffffffffu, s1, o);
            q1 += __shfl_xor_sync(0xffffffffu, q1, o);
        }
        if (tg == 0) {
            red[wg*128 + rl]       = s0; red[512 + wg*128 + rl]     = q0;
            red[wg*128 + rl + 8]   = s1; red[512 + wg*128 + rl + 8] = q1;
        }
    }
    __syncthreads();
    if (tid < 128) {
        float s = red[tid] + red[128+tid] + red[256+tid] + red[384+tid];
        float q = red[512+tid] + red[640+tid] + red[768+tid] + red[896+tid];
        float mean = s * (1.f/256.f);
        red[1024 + tid] = mean;
        red[1152 + tid] = rsqrtf(q * (1.f/256.f) - mean*mean + 1e-5f);
    }
    __syncthreads();
    #pragma unroll
    for (int i = 0; i < 4; i++) {
        const int rl = wm + i*16 + g;
        const float m0v = red[1024 + rl],     rs0 = red[1152 + rl];
        const float m1v = red[1024 + rl + 8], rs1 = red[1152 + rl + 8];
        #pragma unroll
        for (int j = 0; j < 8; j++) {
            const int col = wn + j*8 + tg*2;
            const float ga0 = red[1280 + col], ga1 = red[1281 + col];
            const float be0 = red[1536 + col], be1 = red[1537 + col];
            float2 v0 = make_float2((c[i][j][0]-m0v)*rs0*ga0 + be0,
                                    (c[i][j][1]-m0v)*rs0*ga1 + be1);
            float2 v1 = make_float2((c[i][j][2]-m1v)*rs1*ga0 + be0,
                                    (c[i][j][3]-m1v)*rs1*ga1 + be1);
            *(float2*)&Y[(size_t)rl*ND + col]     = v0;
            *(float2*)&Y[(size_t)(rl+8)*ND + col] = v1;
        }
    }
}

// ============================================================
// Kernel 1: projections.  grid=(128, 6). block tile 128x256, K=256
// Inputs raw fp32 -> cvt in fragments; outputs stored tf32-rounded.
// ============================================================
__global__ __launch_bounds__(256, 1) void proj_mma(
    const float* __restrict__ q_real, const float* __restrict__ q_imag,
    const float* __restrict__ k_real, const float* __restrict__ k_imag,
    const float* __restrict__ v_real, const float* __restrict__ v_imag,
    const float* __restrict__ Wq, const float* __restrict__ bq,
    const float* __restrict__ Wk, const float* __restrict__ bk,
    const float* __restrict__ Wv, const float* __restrict__ bv)
{
    extern __shared__ float smf[];
    const uint32_t sb = smem_u32(smf);
    const int tid = threadIdx.x, lane = tid & 31, wid = tid >> 5;
    const int wm = (wid & 1)*64, wn = (wid >> 1)*64;
    const int m0 = blockIdx.x*128, z = blockIdx.y;
    const float *X, *W, *bias; float* Y;
    switch (z) {
      case 0: X=q_real; W=Wq; bias=bq; Y=g_qr; break;
      case 1: X=q_imag; W=Wq; bias=bq; Y=g_qi; break;
      case 2: X=k_real; W=Wk; bias=bk; Y=g_kr; break;
      case 3: X=k_imag; W=Wk; bias=bk; Y=g_ki; break;
      case 4: X=v_real; W=Wv; bias=bv; Y=g_vr; break;
      default: X=v_imag; W=Wv; bias=bv; Y=g_vi; break;
    }
    const float* Ab = X + (size_t)m0*ND;
    const int CH = 8;
    float c[4][8][4] = {};
    #pragma unroll
    for (int s = 0; s < NSTAGE; s++) {
        cpasyncA(sb + s*BUF_F*4, Ab + s*32, ND, tid);
        cpasyncB(sb + (s*BUF_F + ATILE_F)*4, W + s*32, ND, tid);
        CP_COMMIT;
    }
    int stg = 0;
    for (int ch = 0; ch < CH; ch++) {
        pipe_wait(ch, CH);
        __syncthreads();
        float* base = smf + stg*BUF_F;
        mma_block<true>(base, base + ATILE_F, c, wm, wn, lane);
        __syncthreads();
        if (ch + NSTAGE < CH) {
            cpasyncA(sb + stg*BUF_F*4, Ab + (ch+NSTAGE)*32, ND, tid);
            cpasyncB(sb + (stg*BUF_F + ATILE_F)*4, W + (ch+NSTAGE)*32, ND, tid);
            CP_COMMIT;
        }
        stg = (stg + 1 == NSTAGE) ? 0 : stg + 1;
    }
    epilogue<true>(c, Y, ND, m0, 0, wm, wn, lane, 1.f, bias);
}

// ============================================================
// Kernel 2: V transpose [b][tok][d] -> [b][d][tok] (V pre-rounded)
// ============================================================
__global__ __launch_bounds__(256) void transpose_v()
{
    __shared__ float t[32][33];
    const int b = blockIdx.z & 3, z = blockIdx.z >> 2;
    const float* in = (z ? g_vi : g_vr) + (size_t)b*NL*ND;
    float* outp     = (z ? g_vit : g_vrt) + (size_t)b*ND*NL;
    const int tok0 = blockIdx.x*32, d0 = blockIdx.y*32;
    for (int j = threadIdx.y; j < 32; j += 8)
        t[j][threadIdx.x] = in[(size_t)(tok0 + j)*ND + d0 + threadIdx.x];
    __syncthreads();
    for (int j = threadIdx.y; j < 32; j += 8)
        outp[(size_t)(d0 + j)*NL + tok0 + threadIdx.x] = t[threadIdx.x][j];
}

// ============================================================
// Kernel 3: scores.  grid=(16, 32, 4). block 128x256, K=512
// Operands pre-rounded -> no cvt in mainloop.
// ============================================================
__global__ __launch_bounds__(256, 1) void scores_mma()
{
    extern __shared__ float smf[];
    const uint32_t sb = smem_u32(smf);
    const int tid = threadIdx.x, lane = tid & 31, wid = tid >> 5;
    const int wm = (wid & 1)*64, wn = (wid >> 1)*64;
    const int n0 = blockIdx.x*256, m0 = blockIdx.y*128, b = blockIdx.z;
    const float* APh[2] = { g_qr + (size_t)(b*NL + m0)*ND, g_qi + (size_t)(b*NL + m0)*ND };
    const float* BPh[2] = { g_kr + (size_t)(b*NL + n0)*ND, g_ki + (size_t)(b*NL + n0)*ND };
    const int CH = 16;
    float c[4][8][4] = {};
    #pragma unroll
    for (int s = 0; s < NSTAGE; s++) {
        cpasyncA(sb + s*BUF_F*4, APh[0] + s*32, ND, tid);
        cpasyncB(sb + (s*BUF_F + ATILE_F)*4, BPh[0] + s*32, ND, tid);
        CP_COMMIT;
    }
    int stg = 0;
    for (int ch = 0; ch < CH; ch++) {
        pipe_wait(ch, CH);
        __syncthreads();
        float* base = smf + stg*BUF_F;
        mma_block<false>(base, base + ATILE_F, c, wm, wn, lane);
        __syncthreads();
        if (ch + NSTAGE < CH) {
            const int nc = ch + NSTAGE;
            cpasyncA(sb + stg*BUF_F*4, APh[nc >> 3] + (nc & 7)*32, ND, tid);
            cpasyncB(sb + (stg*BUF_F + ATILE_F)*4, BPh[nc >> 3] + (nc & 7)*32, ND, tid);
            CP_COMMIT;
        }
        stg = (stg + 1 == NSTAGE) ? 0 : stg + 1;
    }
    epilogue<false>(c, g_s + (size_t)b*NL*NL, NL, m0, n0, wm, wn, lane, SCALE, nullptr);
}

// ============================================================
// Kernel 4: softmax with pad mask; writes probs tf32-rounded
// ============================================================
__global__ __launch_bounds__(256) void softmax_kernel(const unsigned char* __restrict__ mask)
{
    __shared__ float sh[8];
    const int row = blockIdx.x, b = row >> 12, t = threadIdx.x;
    float* S = g_s + (size_t)row * NL;
    const unsigned char* m = mask + (size_t)b * NL;
    float v[16];
    #pragma unroll
    for (int j = 0; j < 4; j++) {
        int f4 = t + j*256;
        float4 x = *(const float4*)&S[f4*4];
        uchar4 mk = *(const uchar4*)&m[f4*4];
        v[j*4+0] = mk.x ? -INFINITY : x.x;
        v[j*4+1] = mk.y ? -INFINITY : x.y;
        v[j*4+2] = mk.z ? -INFINITY : x.z;
        v[j*4+3] = mk.w ? -INFINITY : x.w;
    }
    float mx = -INFINITY;
    #pragma unroll
    for (int i = 0; i < 16; i++) mx = fmaxf(mx, v[i]);
    #pragma unroll
    for (int o = 16; o > 0; o >>= 1) mx = fmaxf(mx, __shfl_xor_sync(0xffffffffu, mx, o));
    if ((t & 31) == 0) sh[t >> 5] = mx;
    __syncthreads();
    mx = sh[0];
    #pragma unroll
    for (int i = 1; i < 8; i++) mx = fmaxf(mx, sh[i]);
    __syncthreads();
    float sum = 0.f;
    #pragma unroll
    for (int i = 0; i < 16; i++) { v[i] = __expf(v[i] - mx); sum += v[i]; }
    #pragma unroll
    for (int o = 16; o > 0; o >>= 1) sum += __shfl_xor_sync(0xffffffffu, sum, o);
    if ((t & 31) == 0) sh[t >> 5] = sum;
    __syncthreads();
    sum = 0.f;
    #pragma unroll
    for (int i = 0; i < 8; i++) sum += sh[i];
    const float inv = 1.f / sum;
    #pragma unroll
    for (int j = 0; j < 4; j++) {
        int f4 = t + j*256;
        float4 o;
        o.x = to_tf32(v[j*4+0]*inv); o.y = to_tf32(v[j*4+1]*inv);
        o.z = to_tf32(v[j*4+2]*inv); o.w = to_tf32(v[j*4+3]*inv);
        *(float4*)&S[f4*4] = o;
    }
}

// ============================================================
// Kernel 5: PV + fused LayerNorm.  grid=(2 streams, 32, 4). K=4096
// ============================================================
__global__ __launch_bounds__(256, 1) void pv_mma(
    const float* __restrict__ gamma, const float* __restrict__ beta,
    float* __restrict__ out)
{
    extern __shared__ float smf[];
    const uint32_t sb = smem_u32(smf);
    const int tid = threadIdx.x, lane = tid & 31, wid = tid >> 5;
    const int wm = (wid & 1)*64, wn = (wid >> 1)*64;
    const int stream = blockIdx.x, m0 = blockIdx.y*128, b = blockIdx.z;
    const float* Ab = g_s + (size_t)(b*NL + m0)*NL;
    const float* Bb = (stream ? g_vit : g_vrt) + (size_t)b*ND*NL;
    float* Y = out + (size_t)stream*BLD + (size_t)(b*NL + m0)*ND;
    const int CH = 128;
    float c[4][8][4] = {};
    #pragma unroll
    for (int s = 0; s < NSTAGE; s++) {
        cpasyncA(sb + s*BUF_F*4, Ab + s*32, NL, tid);
        cpasyncB(sb + (s*BUF_F + ATILE_F)*4, Bb + s*32, NL, tid);
        CP_COMMIT;
    }
    int stg = 0;
    for (int ch = 0; ch < CH; ch++) {
        pipe_wait(ch, CH);
        __syncthreads();
        float* base = smf + stg*BUF_F;
        mma_block<false>(base, base + ATILE_F, c, wm, wn, lane);
        __syncthreads();
        if (ch + NSTAGE < CH) {
            cpasyncA(sb + stg*BUF_F*4, Ab + (ch+NSTAGE)*32, NL, tid);
            cpasyncB(sb + (stg*BUF_F + ATILE_F)*4, Bb + (ch+NSTAGE)*32, NL, tid);
            CP_COMMIT;
        }
        stg = (stg + 1 == NSTAGE) ? 0 : stg + 1;
    }
    ln_epilogue(c, smf, gamma, beta, Y, wm, wn, lane, tid, wid);
}

// ============================================================
extern "C" void kernel_launch(void* const* d_in, const int* in_sizes, int n_in,
                              void* d_out, int out_size)
{
    (void)in_sizes; (void)n_in; (void)out_size;
    const float* q_real = (const float*)d_in[0];
    const float* q_imag = (const float*)d_in[1];
    const float* k_real = (const float*)d_in[2];
    const float* k_imag = (const float*)d_in[3];
    const float* v_real = (const float*)d_in[4];
    const float* v_imag = (const float*)d_in[5];
    const unsigned char* pad_mask = (const unsigned char*)d_in[6];
    const float* Wq = (const float*)d_in[7];
    const float* bq = (const float*)d_in[8];
    const float* Wk = (const float*)d_in[9];
    const float* bk = (const float*)d_in[10];
    const float* Wv = (const float*)d_in[11];
    const float* bv = (const float*)d_in[12];
    const float* gamma = (const float*)d_in[13];
    const float* beta  = (const float*)d_in[14];
    float* out = (float*)d_out;

    cudaFuncSetAttribute(proj_mma,   cudaFuncAttributeMaxDynamicSharedMemorySize, SMEM_BYTES);
    cudaFuncSetAttribute(scores_mma, cudaFuncAttributeMaxDynamicSharedMemorySize, SMEM_BYTES);
    cudaFuncSetAttribute(pv_mma,     cudaFuncAttributeMaxDynamicSharedMemorySize, SMEM_BYTES);

    proj_mma<<<dim3(128, 6), 256, SMEM_BYTES>>>(q_real, q_imag, k_real, k_imag,
                                                v_real, v_imag, Wq, bq, Wk, bk, Wv, bv);
    transpose_v<<<dim3(NL/32, ND/32, 8), dim3(32, 8)>>>();
    scores_mma<<<dim3(16, 32, NB), 256, SMEM_BYTES>>>();
    softmax_kernel<<<NB*NL, 256>>>(pad_mask);
    pv_mma<<<dim3(2, 32, NB), 256, SMEM_BYTES>>>(gamma, beta, out);
}

// round 8
// speedup vs baseline: 3.3035x; 1.0047x over previous
#include <cuda_runtime.h>
#include <math.h>
#include <stdint.h>

#define NB 4
#define NL 4096
#define ND 256
#define BLD (NB*NL*ND)
#define SCALE 0.0625f

// ---- scratch (static device globals; allocation is forbidden) ----
__device__ __align__(128) float g_qr[BLD], g_qi[BLD], g_kr[BLD], g_ki[BLD];
__device__ __align__(128) float g_vrt[BLD], g_vit[BLD];    // V transposed [b][d][tok]
__device__ __align__(128) float g_s[(size_t)NB*NL*NL];     // 268MB scores/probs

__device__ __forceinline__ float to_tf32(float x) {
    float y; asm("cvt.rna.tf32.f32 %0, %1;" : "=f"(y) : "f"(x)); return y;
}
__device__ __forceinline__ uint32_t smem_u32(const void* p) {
    uint32_t a;
    asm("{ .reg .u64 t; cvta.to.shared.u64 t, %1; cvt.u32.u64 %0, t; }" : "=r"(a) : "l"(p));
    return a;
}

#define MMA_TF32(c, a, b) \
    asm volatile("mma.sync.aligned.m16n8k8.row.col.f32.tf32.tf32.f32 " \
        "{%0,%1,%2,%3}, {%4,%5,%6,%7}, {%8,%9}, {%0,%1,%2,%3};" \
        : "+f"((c)[0]), "+f"((c)[1]), "+f"((c)[2]), "+f"((c)[3]) \
        : "r"((a)[0]), "r"((a)[1]), "r"((a)[2]), "r"((a)[3]), "r"((b)[0]), "r"((b)[1]))

#define CP_COMMIT asm volatile("cp.async.commit_group;" ::: "memory")
#define CP_WAIT2  asm volatile("cp.async.wait_group 2;" ::: "memory")
#define CP_WAIT1  asm volatile("cp.async.wait_group 1;" ::: "memory")
#define CP_WAIT0  asm volatile("cp.async.wait_group 0;" ::: "memory")

#define LDT 36                    // padded smem row stride (floats)
#define ATILE_F (128*LDT)         // 4608
#define BTILE_F (256*LDT)         // 9216
#define BUF_F (ATILE_F + BTILE_F) // 13824 floats per stage
#define NSTAGE 4
#define SMEM_BYTES (NSTAGE*BUF_F*4)   // 221184 B

// pipeline: need chunk ch done; committed groups = min(ch+3, CH)
#define PIPE_WAIT(ch, CH) do { \
    if ((ch) + 3 <= (CH)) CP_WAIT2; \
    else if ((ch) + 2 == (CH)) CP_WAIT1; \
    else CP_WAIT0; } while (0)

// ---- cp.async tile loaders (raw fp32; operands pre-rounded to tf32) ----
__device__ __forceinline__ void cpasyncA(uint32_t dstbase, const float* __restrict__ p,
                                         size_t ld, int tid) {
    #pragma unroll
    for (int i = 0; i < 4; i++) {
        int pos = tid + i*256, row = pos >> 3, c4 = pos & 7;
        uint32_t dst = dstbase + (uint32_t)(row*LDT + c4*4)*4u;
        asm volatile("cp.async.cg.shared.global [%0], [%1], 16;"
                     :: "r"(dst), "l"(p + (size_t)row*ld + c4*4));
    }
}
__device__ __forceinline__ void cpasyncB(uint32_t dstbase, const float* __restrict__ p,
                                         size_t ld, int tid) {
    #pragma unroll
    for (int i = 0; i < 8; i++) {
        int pos = tid + i*256, row = pos >> 3, c4 = pos & 7;
        uint32_t dst = dstbase + (uint32_t)(row*LDT + c4*4)*4u;
        asm volatile("cp.async.cg.shared.global [%0], [%1], 16;"
                     :: "r"(dst), "l"(p + (size_t)row*ld + c4*4));
    }
}

// ---- one 128x256x32 block step; warp tile 64x64 ----
template<bool CVT>
__device__ __forceinline__ void mma_block(const float* As, const float* Bs,
                                          float c[4][8][4], int wm, int wn, int lane)
{
    const int g = lane >> 2, tg = lane & 3;
    #pragma unroll
    for (int k8 = 0; k8 < 4; k8++) {
        const int k0 = k8*8;
        uint32_t a[4][4];
        #pragma unroll
        for (int i = 0; i < 4; i++) {
            const float* ap = As + (wm + i*16 + g)*LDT + k0 + tg;
            float f0 = ap[0], f1 = ap[8*LDT], f2 = ap[4], f3 = ap[8*LDT + 4];
            if (CVT) { f0 = to_tf32(f0); f1 = to_tf32(f1); f2 = to_tf32(f2); f3 = to_tf32(f3); }
            a[i][0] = __float_as_uint(f0);
            a[i][1] = __float_as_uint(f1);
            a[i][2] = __float_as_uint(f2);
            a[i][3] = __float_as_uint(f3);
        }
        #pragma unroll
        for (int j = 0; j < 8; j++) {
            const float* bp = Bs + (wn + j*8 + g)*LDT + k0 + tg;
            float f0 = bp[0], f1 = bp[4];
            if (CVT) { f0 = to_tf32(f0); f1 = to_tf32(f1); }
            uint32_t b[2] = { __float_as_uint(f0), __float_as_uint(f1) };
            #pragma unroll
            for (int i = 0; i < 4; i++) MMA_TF32(c[i][j], a[i], b);
        }
    }
}

// generic epilogue (proj Q/K, scores).  ROUND: store tf32-rounded values.
template<bool ROUND>
__device__ __forceinline__ void epilogue(float c[4][8][4], float* __restrict__ out,
                                         size_t ldm, int m0, int n0, int wm, int wn,
                                         int lane, float scale, const float* __restrict__ bias)
{
    const int g = lane >> 2, tg = lane & 3;
    #pragma unroll
    for (int i = 0; i < 4; i++) {
        const int r0 = m0 + wm + i*16 + g;
        #pragma unroll
        for (int j = 0; j < 8; j++) {
            const int col = n0 + wn + j*8 + tg*2;
            float b0 = 0.f, b1 = 0.f;
            if (bias) { b0 = bias[col]; b1 = bias[col+1]; }
            float v00 = c[i][j][0]*scale + b0, v01 = c[i][j][1]*scale + b1;
            float v10 = c[i][j][2]*scale + b0, v11 = c[i][j][3]*scale + b1;
            if (ROUND) { v00 = to_tf32(v00); v01 = to_tf32(v01);
                         v10 = to_tf32(v10); v11 = to_tf32(v11); }
            *(float2*)&out[(size_t)r0*ldm + col]     = make_float2(v00, v01);
            *(float2*)&out[(size_t)(r0+8)*ldm + col] = make_float2(v10, v11);
        }
    }
}

// V epilogue: stage tile in smem, store TRANSPOSED to Yt[d][tok] (tf32-rounded).
// Yt must already point at this batch's [ND][NL] slab; tok0 is the in-batch token base.
#define VST 257
__device__ __forceinline__ void vt_epilogue(float c[4][8][4], float* stg,
                                            const float* __restrict__ bias,
                                            float* __restrict__ Yt,
                                            int tok0, int wm, int wn, int lane, int wid)
{
    const int g = lane >> 2, tg = lane & 3;
    __syncthreads();                  // mainloop smem free
    #pragma unroll
    for (int i = 0; i < 4; i++) {
        const int r0 = wm + i*16 + g;
        #pragma unroll
        for (int j = 0; j < 8; j++) {
            const int col = wn + j*8 + tg*2;
            const float b0 = bias[col], b1 = bias[col+1];
            stg[r0*VST + col]       = to_tf32(c[i][j][0] + b0);
            stg[r0*VST + col+1]     = to_tf32(c[i][j][1] + b1);
            stg[(r0+8)*VST + col]   = to_tf32(c[i][j][2] + b0);
            stg[(r0+8)*VST + col+1] = to_tf32(c[i][j][3] + b1);
        }
    }
    __syncthreads();
    #pragma unroll
    for (int dd = 0; dd < 32; dd++) {
        const int d = wid*32 + dd;
        float4 v;
        v.x = stg[(lane*4+0)*VST + d];
        v.y = stg[(lane*4+1)*VST + d];
        v.z = stg[(lane*4+2)*VST + d];
        v.w = stg[(lane*4+3)*VST + d];
        *(float4*)&Yt[(size_t)d*NL + tok0 + lane*4] = v;
    }
}

// PV epilogue: cross-warp LayerNorm over the 256 block cols, then store
__device__ __forceinline__ void ln_epilogue(float c[4][8][4], float* red,
                                            const float* __restrict__ gamma,
                                            const float* __restrict__ beta,
                                            float* __restrict__ Y,
                                            int wm, int wn, int lane, int tid, int wid)
{
    const int g = lane >> 2, tg = lane & 3;
    const int wg = wid >> 1;          // n-warp group 0..3
    __syncthreads();                  // main loop done; smem free
    red[1280 + tid] = gamma[tid];
    red[1536 + tid] = beta[tid];
    #pragma unroll
    for (int i = 0; i < 4; i++) {
        const int rl = wm + i*16 + g;
        float s0 = 0.f, q0 = 0.f, s1 = 0.f, q1 = 0.f;
        #pragma unroll
        for (int j = 0; j < 8; j++) {
            s0 += c[i][j][0] + c[i][j][1];
            q0 += c[i][j][0]*c[i][j][0] + c[i][j][1]*c[i][j][1];
            s1 += c[i][j][2] + c[i][j][3];
            q1 += c[i][j][2]*c[i][j][2] + c[i][j][3]*c[i][j][3];
        }
        #pragma unroll
        for (int o = 1; o < 4; o <<= 1) {
            s0 += __shfl_xor_sync(0xffffffffu, s0, o);
            q0 += __shfl_xor_sync(0xffffffffu, q0, o);
            s1 += __shfl_xor_sync(0xffffffffu, s1, o);
            q1 += __shfl_xor_sync(0xffffffffu, q1, o);
        }
        if (tg == 0) {
            red[wg*128 + rl]       = s0; red[512 + wg*128 + rl]     = q0;
            red[wg*128 + rl + 8]   = s1; red[512 + wg*128 + rl + 8] = q1;
        }
    }
    __syncthreads();
    if (tid < 128) {
        float s = red[tid] + red[128+tid] + red[256+tid] + red[384+tid];
        float q = red[512+tid] + red[640+tid] + red[768+tid] + red[896+tid];
        float mean = s * (1.f/256.f);
        red[1024 + tid] = mean;
        red[1152 + tid] = rsqrtf(q * (1.f/256.f) - mean*mean + 1e-5f);
    }
    __syncthreads();
    #pragma unroll
    for (int i = 0; i < 4; i++) {
        const int rl = wm + i*16 + g;
        const float m0v = red[1024 + rl],     rs0 = red[1152 + rl];
        const float m1v = red[1024 + rl + 8], rs1 = red[1152 + rl + 8];
        #pragma unroll
        for (int j = 0; j < 8; j++) {
            const int col = wn + j*8 + tg*2;
            const float ga0 = red[1280 + col], ga1 = red[1281 + col];
            const float be0 = red[1536 + col], be1 = red[1537 + col];
            float2 v0 = make_float2((c[i][j][0]-m0v)*rs0*ga0 + be0,
                                    (c[i][j][1]-m0v)*rs0*ga1 + be1);
            float2 v1 = make_float2((c[i][j][2]-m1v)*rs1*ga0 + be0,
                                    (c[i][j][3]-m1v)*rs1*ga1 + be1);
            *(float2*)&Y[(size_t)rl*ND + col]     = v0;
            *(float2*)&Y[(size_t)(rl+8)*ND + col] = v1;
        }
    }
}

// ============================================================
// Kernel 1: projections.  grid=(128, 6). block 128x256, K=256.
// V streams (z=4,5) write TRANSPOSED output directly.
// ============================================================
__global__ __launch_bounds__(256, 1) void proj_mma(
    const float* __restrict__ q_real, const float* __restrict__ q_imag,
    const float* __restrict__ k_real, const float* __restrict__ k_imag,
    const float* __restrict__ v_real, const float* __restrict__ v_imag,
    const float* __restrict__ Wq, const float* __restrict__ bq,
    const float* __restrict__ Wk, const float* __restrict__ bk,
    const float* __restrict__ Wv, const float* __restrict__ bv)
{
    extern __shared__ float smf[];
    const uint32_t sb = smem_u32(smf);
    const int tid = threadIdx.x, lane = tid & 31, wid = tid >> 5;
    const int wm = (wid & 1)*64, wn = (wid >> 1)*64;
    const int m0 = blockIdx.x*128, z = blockIdx.y;
    const float *X, *W, *bias; float* Y;
    switch (z) {
      case 0: X=q_real; W=Wq; bias=bq; Y=g_qr; break;
      case 1: X=q_imag; W=Wq; bias=bq; Y=g_qi; break;
      case 2: X=k_real; W=Wk; bias=bk; Y=g_kr; break;
      case 3: X=k_imag; W=Wk; bias=bk; Y=g_ki; break;
      case 4: X=v_real; W=Wv; bias=bv; Y=g_vrt; break;
      default: X=v_imag; W=Wv; bias=bv; Y=g_vit; break;
    }
    const float* Ab = X + (size_t)m0*ND;
    const int CH = 8;
    float c[4][8][4] = {};
    #pragma unroll
    for (int s = 0; s < 3; s++) {
        cpasyncA(sb + s*BUF_F*4, Ab + s*32, ND, tid);
        cpasyncB(sb + (s*BUF_F + ATILE_F)*4, W + s*32, ND, tid);
        CP_COMMIT;
    }
    #pragma unroll 1
    for (int ch = 0; ch < CH; ch++) {
        PIPE_WAIT(ch, CH);
        __syncthreads();
        if (ch + 3 < CH) {
            const int s = (ch+3) & 3;
            cpasyncA(sb + s*BUF_F*4, Ab + (ch+3)*32, ND, tid);
            cpasyncB(sb + (s*BUF_F + ATILE_F)*4, W + (ch+3)*32, ND, tid);
            CP_COMMIT;
        }
        float* base = smf + (ch & 3)*BUF_F;
        mma_block<true>(base, base + ATILE_F, c, wm, wn, lane);
    }
    if (z < 4) {
        epilogue<true>(c, Y, ND, m0, 0, wm, wn, lane, 1.f, bias);
    } else {
        // decompose global row -> (batch, in-batch token) for [b][d][tok] layout
        const int b = m0 >> 12, tok0 = m0 & (NL - 1);
        vt_epilogue(c, smf, bias, Y + (size_t)b*ND*NL, tok0, wm, wn, lane, wid);
    }
}

// ============================================================
// Kernel 2: scores.  grid=(16, 32, 4). block 128x256, K=512
// ============================================================
__global__ __launch_bounds__(256, 1) void scores_mma()
{
    extern __shared__ float smf[];
    const uint32_t sb = smem_u32(smf);
    const int tid = threadIdx.x, lane = tid & 31, wid = tid >> 5;
    const int wm = (wid & 1)*64, wn = (wid >> 1)*64;
    const int n0 = blockIdx.x*256, m0 = blockIdx.y*128, b = blockIdx.z;
    const float* APh[2] = { g_qr + (size_t)(b*NL + m0)*ND, g_qi + (size_t)(b*NL + m0)*ND };
    const float* BPh[2] = { g_kr + (size_t)(b*NL + n0)*ND, g_ki + (size_t)(b*NL + n0)*ND };
    const int CH = 16;
    float c[4][8][4] = {};
    #pragma unroll
    for (int s = 0; s < 3; s++) {
        cpasyncA(sb + s*BUF_F*4, APh[0] + s*32, ND, tid);
        cpasyncB(sb + (s*BUF_F + ATILE_F)*4, BPh[0] + s*32, ND, tid);
        CP_COMMIT;
    }
    #pragma unroll 1
    for (int ch = 0; ch < CH; ch++) {
        PIPE_WAIT(ch, CH);
        __syncthreads();
        if (ch + 3 < CH) {
            const int nc = ch + 3, s = nc & 3;
            cpasyncA(sb + s*BUF_F*4, APh[nc >> 3] + (nc & 7)*32, ND, tid);
            cpasyncB(sb + (s*BUF_F + ATILE_F)*4, BPh[nc >> 3] + (nc & 7)*32, ND, tid);
            CP_COMMIT;
        }
        float* base = smf + (ch & 3)*BUF_F;
        mma_block<false>(base, base + ATILE_F, c, wm, wn, lane);
    }
    epilogue<false>(c, g_s + (size_t)b*NL*NL, NL, m0, n0, wm, wn, lane, SCALE, nullptr);
}

// ============================================================
// Kernel 3: softmax with pad mask; writes probs tf32-rounded
// ============================================================
__global__ __launch_bounds__(256) void softmax_kernel(const unsigned char* __restrict__ mask)
{
    __shared__ float sh[8];
    const int row = blockIdx.x, b = row >> 12, t = threadIdx.x;
    float* S = g_s + (size_t)row * NL;
    const unsigned char* m = mask + (size_t)b * NL;
    float v[16];
    #pragma unroll
    for (int j = 0; j < 4; j++) {
        int f4 = t + j*256;
        float4 x = *(const float4*)&S[f4*4];
        uchar4 mk = *(const uchar4*)&m[f4*4];
        v[j*4+0] = mk.x ? -INFINITY : x.x;
        v[j*4+1] = mk.y ? -INFINITY : x.y;
        v[j*4+2] = mk.z ? -INFINITY : x.z;
        v[j*4+3] = mk.w ? -INFINITY : x.w;
    }
    float mx = -INFINITY;
    #pragma unroll
    for (int i = 0; i < 16; i++) mx = fmaxf(mx, v[i]);
    #pragma unroll
    for (int o = 16; o > 0; o >>= 1) mx = fmaxf(mx, __shfl_xor_sync(0xffffffffu, mx, o));
    if ((t & 31) == 0) sh[t >> 5] = mx;
    __syncthreads();
    mx = sh[0];
    #pragma unroll
    for (int i = 1; i < 8; i++) mx = fmaxf(mx, sh[i]);
    __syncthreads();
    float sum = 0.f;
    #pragma unroll
    for (int i = 0; i < 16; i++) { v[i] = __expf(v[i] - mx); sum += v[i]; }
    #pragma unroll
    for (int o = 16; o > 0; o >>= 1) sum += __shfl_xor_sync(0xffffffffu, sum, o);
    if ((t & 31) == 0) sh[t >> 5] = sum;
    __syncthreads();
    sum = 0.f;
    #pragma unroll
    for (int i = 0; i < 8; i++) sum += sh[i];
    const float inv = 1.f / sum;
    #pragma unroll
    for (int j = 0; j < 4; j++) {
        int f4 = t + j*256;
        float4 o;
        o.x = to_tf32(v[j*4+0]*inv); o.y = to_tf32(v[j*4+1]*inv);
        o.z = to_tf32(v[j*4+2]*inv); o.w = to_tf32(v[j*4+3]*inv);
        *(float4*)&S[f4*4] = o;
    }
}

// ============================================================
// Kernel 4: PV + fused LayerNorm.  grid=(2 streams, 32, 4). K=4096
// ============================================================
__global__ __launch_bounds__(256, 1) void pv_mma(
    const float* __restrict__ gamma, const float* __restrict__ beta,
    float* __restrict__ out)
{
    extern __shared__ float smf[];
    const uint32_t sb = smem_u32(smf);
    const int tid = threadIdx.x, lane = tid & 31, wid = tid >> 5;
    const int wm = (wid & 1)*64, wn = (wid >> 1)*64;
    const int stream = blockIdx.x, m0 = blockIdx.y*128, b = blockIdx.z;
    const float* Ab = g_s + (size_t)(b*NL + m0)*NL;
    const float* Bb = (stream ? g_vit : g_vrt) + (size_t)b*ND*NL;
    float* Y = out + (size_t)stream*BLD + (size_t)(b*NL + m0)*ND;
    const int CH = 128;
    float c[4][8][4] = {};
    #pragma unroll
    for (int s = 0; s < 3; s++) {
        cpasyncA(sb + s*BUF_F*4, Ab + s*32, NL, tid);
        cpasyncB(sb + (s*BUF_F + ATILE_F)*4, Bb + s*32, NL, tid);
        CP_COMMIT;
    }
    #pragma unroll 1
    for (int ch = 0; ch < CH; ch++) {
        PIPE_WAIT(ch, CH);
        __syncthreads();
        if (ch + 3 < CH) {
            const int s = (ch+3) & 3;
            cpasyncA(sb + s*BUF_F*4, Ab + (ch+3)*32, NL, tid);
            cpasyncB(sb + (s*BUF_F + ATILE_F)*4, Bb + (ch+3)*32, NL, tid);
            CP_COMMIT;
        }
        float* base = smf + (ch & 3)*BUF_F;
        mma_block<false>(base, base + ATILE_F, c, wm, wn, lane);
    }
    ln_epilogue(c, smf, gamma, beta, Y, wm, wn, lane, tid, wid);
}

// ============================================================
extern "C" void kernel_launch(void* const* d_in, const int* in_sizes, int n_in,
                              void* d_out, int out_size)
{
    (void)in_sizes; (void)n_in; (void)out_size;
    const float* q_real = (const float*)d_in[0];
    const float* q_imag = (const float*)d_in[1];
    const float* k_real = (const float*)d_in[2];
    const float* k_imag = (const float*)d_in[3];
    const float* v_real = (const float*)d_in[4];
    const float* v_imag = (const float*)d_in[5];
    const unsigned char* pad_mask = (const unsigned char*)d_in[6];
    const float* Wq = (const float*)d_in[7];
    const float* bq = (const float*)d_in[8];
    const float* Wk = (const float*)d_in[9];
    const float* bk = (const float*)d_in[10];
    const float* Wv = (const float*)d_in[11];
    const float* bv = (const float*)d_in[12];
    const float* gamma = (const float*)d_in[13];
    const float* beta  = (const float*)d_in[14];
    float* out = (float*)d_out;

    cudaFuncSetAttribute(proj_mma,   cudaFuncAttributeMaxDynamicSharedMemorySize, SMEM_BYTES);
    cudaFuncSetAttribute(scores_mma, cudaFuncAttributeMaxDynamicSharedMemorySize, SMEM_BYTES);
    cudaFuncSetAttribute(pv_mma,     cudaFuncAttributeMaxDynamicSharedMemorySize, SMEM_BYTES);

    proj_mma<<<dim3(128, 6), 256, SMEM_BYTES>>>(q_real, q_imag, k_real, k_imag,
                                                v_real, v_imag, Wq, bq, Wk, bk, Wv, bv);
    scores_mma<<<dim3(16, 32, NB), 256, SMEM_BYTES>>>();
    softmax_kernel<<<NB*NL, 256>>>(pad_mask);
    pv_mma<<<dim3(2, 32, NB), 256, SMEM_BYTES>>>(gamma, beta, out);
}